// round 4
// baseline (speedup 1.0000x reference)
#include <cuda_runtime.h>
#include <cuda_bf16.h>
#include <math.h>
#include <stdint.h>

// Problem constants
#define B_SZ 8
#define T_SZ 2048
#define C_SZ 1024
#define H_SZ 64
#define WIN 64
#define NGLOB 64
#define NRAND 64

#define BT (B_SZ * T_SZ)          // 16384 rows

// Scratch for projected q, k, v  (4 MB each) — device globals, no allocation.
__device__ float g_Q[BT * H_SZ];
__device__ float g_K[BT * H_SZ];
__device__ float g_V[BT * H_SZ];

// ---------------------------------------------------------------------------
// tf32 helpers
// ---------------------------------------------------------------------------
__device__ __forceinline__ uint32_t f2tf32(float f) {
    uint32_t r;
    asm("cvt.rna.tf32.f32 %0, %1;" : "=r"(r) : "f"(f));
    return r;
}

__device__ __forceinline__ void mma_tf32(float* c, const uint32_t* a, const uint32_t* b) {
    asm volatile(
        "mma.sync.aligned.m16n8k8.row.col.f32.tf32.tf32.f32 "
        "{%0,%1,%2,%3}, {%4,%5,%6,%7}, {%8,%9}, {%0,%1,%2,%3};"
        : "+f"(c[0]), "+f"(c[1]), "+f"(c[2]), "+f"(c[3])
        : "r"(a[0]), "r"(a[1]), "r"(a[2]), "r"(a[3]),
          "r"(b[0]), "r"(b[1]));
}

// ---------------------------------------------------------------------------
// FUSED projection GEMM (Q, K, V in one kernel) via 3xTF32-split mma.sync.
//   out[m][h] = sum_c x[m][c] * W[h][c],  M=16384, K=1024, N=3x64
// Block: 128(M) x 192(N-total) x 8(K-chunk), 256 threads = 8 warps.
// Each warp: 16 M-rows x 24 n-tiles (8 per output matrix).
//
// smem layout: per row, 8 k-words stored PAIR-PERMUTED: word position
// j*2+half holds k = j + half*4 (j=0..3, half=0..1), so the MMA fragment
// pair (k, k+4) is ADJACENT -> all fragment loads are LDS.64.
// Row stride 12 words: 12*g mod 32 = {0,12,24,4,16,28,8,20} distinct ->
// LDS.64 fragment gathers and STS.128 fills are bank-conflict-free.
// ---------------------------------------------------------------------------
#define KC 8
#define PADK 12

__global__ __launch_bounds__(256) void proj_tc_kernel(
    const float* __restrict__ x,
    const float* __restrict__ Wq,
    const float* __restrict__ Wk,
    const float* __restrict__ Wv)
{
    __shared__ __align__(16) uint32_t xh[128][PADK];
    __shared__ __align__(16) uint32_t xl[128][PADK];
    __shared__ __align__(16) uint32_t wh[192][PADK];
    __shared__ __align__(16) uint32_t wl[192][PADK];

    const int m0   = blockIdx.x * 128;
    const int tid  = threadIdx.x;
    const int warp = tid >> 5;
    const int lane = tid & 31;
    const int grp  = lane >> 2;   // 0..7
    const int tig  = lane & 3;    // 0..3

    float acc[24][4];
#pragma unroll
    for (int nt = 0; nt < 24; nt++)
#pragma unroll
        for (int j = 0; j < 4; j++) acc[nt][j] = 0.f;

    for (int k0 = 0; k0 < C_SZ; k0 += KC) {
        // ---- x fill: 128 rows, one row per thread (threads 0..127) ----
        if (tid < 128) {
            const float* xp = &x[(size_t)(m0 + tid) * C_SZ + k0];
            float4 f0 = *(const float4*)xp;
            float4 f4 = *(const float4*)(xp + 4);
            float a[8] = {f0.x, f4.x, f0.y, f4.y, f0.z, f4.z, f0.w, f4.w};
            uint32_t hi[8], lo[8];
#pragma unroll
            for (int j = 0; j < 8; j++) {
                hi[j] = f2tf32(a[j]);
                lo[j] = f2tf32(a[j] - __uint_as_float(hi[j]));
            }
            *(uint4*)&xh[tid][0] = make_uint4(hi[0], hi[1], hi[2], hi[3]);
            *(uint4*)&xh[tid][4] = make_uint4(hi[4], hi[5], hi[6], hi[7]);
            *(uint4*)&xl[tid][0] = make_uint4(lo[0], lo[1], lo[2], lo[3]);
            *(uint4*)&xl[tid][4] = make_uint4(lo[4], lo[5], lo[6], lo[7]);
        } else {
            // ---- W fill: 192 rows, threads 128..255 handle rows in 2 waves
            // rows: 0-63 Wq, 64-127 Wk, 128-191 Wv
            int rt = tid - 128;   // 0..127
#pragma unroll
            for (int it = 0; it < 2; it++) {
                int row = rt + it * 96;          // covers 0..223, clip to 192
                if (row < 192) {
                    const float* wp;
                    if (row < 64)       wp = &Wq[(size_t)row * C_SZ + k0];
                    else if (row < 128) wp = &Wk[(size_t)(row - 64) * C_SZ + k0];
                    else                wp = &Wv[(size_t)(row - 128) * C_SZ + k0];
                    float4 f0 = *(const float4*)wp;
                    float4 f4 = *(const float4*)(wp + 4);
                    float a[8] = {f0.x, f4.x, f0.y, f4.y, f0.z, f4.z, f0.w, f4.w};
                    uint32_t hi[8], lo[8];
#pragma unroll
                    for (int j = 0; j < 8; j++) {
                        hi[j] = f2tf32(a[j]);
                        lo[j] = f2tf32(a[j] - __uint_as_float(hi[j]));
                    }
                    *(uint4*)&wh[row][0] = make_uint4(hi[0], hi[1], hi[2], hi[3]);
                    *(uint4*)&wh[row][4] = make_uint4(hi[4], hi[5], hi[6], hi[7]);
                    *(uint4*)&wl[row][0] = make_uint4(lo[0], lo[1], lo[2], lo[3]);
                    *(uint4*)&wl[row][4] = make_uint4(lo[4], lo[5], lo[6], lo[7]);
                }
            }
        }
        __syncthreads();

        // ---- fragments + MMA ----
        const int mw = warp * 16;
        // a-frags: pair (k=tig, k=tig+4) adjacent -> LDS.64
        uint32_t ah[4], al[4];
        {
            uint2 p0 = *(const uint2*)&xh[mw + grp][tig * 2];      // (ah0, ah2)
            uint2 p1 = *(const uint2*)&xh[mw + grp + 8][tig * 2];  // (ah1, ah3)
            ah[0] = p0.x; ah[2] = p0.y; ah[1] = p1.x; ah[3] = p1.y;
            uint2 q0 = *(const uint2*)&xl[mw + grp][tig * 2];
            uint2 q1 = *(const uint2*)&xl[mw + grp + 8][tig * 2];
            al[0] = q0.x; al[2] = q0.y; al[1] = q1.x; al[3] = q1.y;
        }
#pragma unroll
        for (int nt = 0; nt < 24; nt++) {
            const int wrow = nt * 8 + grp;
            uint2 bh2 = *(const uint2*)&wh[wrow][tig * 2];
            uint2 bl2 = *(const uint2*)&wl[wrow][tig * 2];
            uint32_t bh[2] = {bh2.x, bh2.y};
            uint32_t bl[2] = {bl2.x, bl2.y};
            mma_tf32(acc[nt], al, bh);   // lo*hi
            mma_tf32(acc[nt], ah, bl);   // hi*lo
            mma_tf32(acc[nt], ah, bh);   // hi*hi
        }
        __syncthreads();
    }

    // epilogue: c0=(grp, 2*tig), c1=(grp, 2*tig+1), c2=(grp+8, ...), c3=+1
    const int mw = m0 + warp * 16;
#pragma unroll
    for (int nt = 0; nt < 24; nt++) {
        float* out = (nt < 8) ? g_Q : (nt < 16) ? g_K : g_V;
        int col = (nt & 7) * 8 + tig * 2;
        float2 v01 = make_float2(acc[nt][0], acc[nt][1]);
        float2 v23 = make_float2(acc[nt][2], acc[nt][3]);
        *(float2*)&out[(size_t)(mw + grp) * H_SZ + col]     = v01;
        *(float2*)&out[(size_t)(mw + grp + 8) * H_SZ + col] = v23;
    }
}

// ---------------------------------------------------------------------------
// Sparse BigBird attention (UNCHANGED from passing round-3 version).
// ---------------------------------------------------------------------------
__global__ __launch_bounds__(256) void attn_kernel(
    const int* __restrict__ random_cols,
    float* __restrict__ out)
{
    const int g = blockIdx.x;          // 0 .. BT-1
    const int b = g >> 11;             // T = 2048
    const int r = g & (T_SZ - 1);

    __shared__ int   cols[192];
    __shared__ float sc[192];
    __shared__ __align__(16) float qs[H_SZ];
    __shared__ int   rnd[NRAND];
    __shared__ int   s_nrand;
    __shared__ float red[8];
    __shared__ float s_mx, s_inv;
    __shared__ __align__(16) float outp[16][H_SZ];

    const int tid  = threadIdx.x;
    const int lane = tid & 31;
    const int warp = tid >> 5;

    if (tid < H_SZ) {
        qs[tid]  = g_Q[(size_t)g * H_SZ + tid];
        rnd[tid] = random_cols[r * NRAND + tid];
    }
    if (tid == 0) s_nrand = 0;

    const int lo = max(0, r - (WIN - 1));
    const int nl = r - lo + 1;              // local count (<=64)
    const int ng = min(NGLOB, lo);          // global count (no local overlap)

    __syncthreads();

    if (tid < nl)                   cols[tid] = lo + tid;
    if (tid >= 64 && tid < 64 + ng) cols[nl + (tid - 64)] = tid - 64;
    if (tid >= 128 && tid < 128 + NRAND) {
        int i = tid - 128;
        int c = rnd[i];
        bool valid = (c >= ng) && (c < lo);   // causal + not already covered
        if (valid) {
            for (int j = 0; j < i; j++)
                if (rnd[j] == c) { valid = false; break; }
        }
        if (valid) {
            int p = atomicAdd(&s_nrand, 1);
            cols[nl + ng + p] = c;
        }
    }
    __syncthreads();
    const int n = nl + ng + s_nrand;

    // ---- scores: 8-lane groups, warp-uniform trip count ----
    const int l8 = lane & 7;
    const int g8 = lane >> 3;
    const float4 qa = *(const float4*)&qs[l8 * 8];
    const float4 qb = *(const float4*)&qs[l8 * 8 + 4];
    const size_t bbase = (size_t)b * T_SZ;

    for (int ci0 = warp * 4; ci0 < n; ci0 += 32) {
        int  ci  = ci0 + g8;
        bool act = (ci < n);
        int  c   = cols[act ? ci : 0];
        const float* kp = &g_K[(bbase + c) * H_SZ + l8 * 8];
        float4 ka = *(const float4*)kp;
        float4 kb = *(const float4*)(kp + 4);
        float p = qa.x * ka.x + qa.y * ka.y + qa.z * ka.z + qa.w * ka.w
                + qb.x * kb.x + qb.y * kb.y + qb.z * kb.z + qb.w * kb.w;
        p += __shfl_xor_sync(0xffffffffu, p, 4);
        p += __shfl_xor_sync(0xffffffffu, p, 2);
        p += __shfl_xor_sync(0xffffffffu, p, 1);
        if (l8 == 0 && act) sc[ci] = p * 0.125f;   // 1/sqrt(64)
    }
    __syncthreads();

    // ---- softmax: max ----
    float mx = -1e30f;
    for (int i = tid; i < n; i += 256) mx = fmaxf(mx, sc[i]);
#pragma unroll
    for (int o = 16; o; o >>= 1) mx = fmaxf(mx, __shfl_xor_sync(0xffffffffu, mx, o));
    if (lane == 0) red[warp] = mx;
    __syncthreads();
    if (tid == 0) {
        float m = red[0];
#pragma unroll
        for (int w = 1; w < 8; w++) m = fmaxf(m, red[w]);
        s_mx = m;
    }
    __syncthreads();
    const float smx = s_mx;

    // ---- exp + sum ----
    float sm = 0.f;
    for (int i = tid; i < n; i += 256) {
        float e = __expf(sc[i] - smx);
        sc[i] = e;
        sm += e;
    }
#pragma unroll
    for (int o = 16; o; o >>= 1) sm += __shfl_xor_sync(0xffffffffu, sm, o);
    if (lane == 0) red[warp] = sm;
    __syncthreads();
    if (tid == 0) {
        float s = 0.f;
#pragma unroll
        for (int w = 0; w < 8; w++) s += red[w];
        s_inv = 1.0f / s;
    }
    __syncthreads();
    const float inv = s_inv;

    // ---- output: 16 groups of 16 threads, float4 over head dim ----
    const int dg = tid & 15;
    const int gq = tid >> 4;
    float4 a4 = make_float4(0.f, 0.f, 0.f, 0.f);
    for (int i = gq; i < n; i += 16) {
        float w = sc[i];
        float4 v4 = *(const float4*)&g_V[(bbase + cols[i]) * H_SZ + dg * 4];
        a4.x += w * v4.x;
        a4.y += w * v4.y;
        a4.z += w * v4.z;
        a4.w += w * v4.w;
    }
    *(float4*)&outp[gq][dg * 4] = a4;
    __syncthreads();

    if (tid < H_SZ) {
        float o = 0.f;
#pragma unroll
        for (int k = 0; k < 16; k++) o += outp[k][tid];
        out[(size_t)g * H_SZ + tid] = o * inv;
    }
}

// ---------------------------------------------------------------------------
// kernel_launch — inputs per metadata order: x, random_cols, Wk, Wq, Wv
// ---------------------------------------------------------------------------
extern "C" void kernel_launch(void* const* d_in, const int* in_sizes, int n_in,
                              void* d_out, int out_size)
{
    const float* x           = (const float*)d_in[0];
    const int*   random_cols = (const int*)  d_in[1];
    const float* Wk          = (const float*)d_in[2];
    const float* Wq          = (const float*)d_in[3];
    const float* Wv          = (const float*)d_in[4];
    float* out = (float*)d_out;

    proj_tc_kernel<<<BT / 128, 256>>>(x, Wq, Wk, Wv);

    attn_kernel<<<BT, 256>>>(random_cols, out);
}

// round 5
// speedup vs baseline: 1.3034x; 1.3034x over previous
#include <cuda_runtime.h>
#include <cuda_bf16.h>
#include <math.h>
#include <stdint.h>

// Problem constants
#define B_SZ 8
#define T_SZ 2048
#define C_SZ 1024
#define H_SZ 64
#define WIN 64
#define NGLOB 64
#define NRAND 64

#define BT (B_SZ * T_SZ)          // 16384 rows

// Scratch for projected q, k, v  (4 MB each) — device globals, no allocation.
__device__ float g_Q[BT * H_SZ];
__device__ float g_K[BT * H_SZ];
__device__ float g_V[BT * H_SZ];

// ---------------------------------------------------------------------------
// tf32 helpers
// ---------------------------------------------------------------------------
__device__ __forceinline__ uint32_t f2tf32(float f) {
    uint32_t r;
    asm("cvt.rna.tf32.f32 %0, %1;" : "=r"(r) : "f"(f));
    return r;
}

__device__ __forceinline__ void mma_tf32(float* c, const uint32_t* a, const uint32_t* b) {
    asm volatile(
        "mma.sync.aligned.m16n8k8.row.col.f32.tf32.tf32.f32 "
        "{%0,%1,%2,%3}, {%4,%5,%6,%7}, {%8,%9}, {%0,%1,%2,%3};"
        : "+f"(c[0]), "+f"(c[1]), "+f"(c[2]), "+f"(c[3])
        : "r"(a[0]), "r"(a[1]), "r"(a[2]), "r"(a[3]),
          "r"(b[0]), "r"(b[1]));
}

// ---------------------------------------------------------------------------
// FUSED projection GEMM (Q,K,V) via 3xTF32-split mma.sync + REGISTER
// DOUBLE-BUFFERING: next chunk's global loads are issued before the MMA
// phase of the current chunk, so LDG latency hides under MMA/LDS work.
// Layout identical to the (numerically verified) round-4 kernel:
// pair-permuted smem rows (k and k+4 adjacent -> LDS.64 fragments),
// row stride 12 words -> conflict-free STS.128 fills and LDS.64 gathers.
// ---------------------------------------------------------------------------
#define KC 8
#define PADK 12

__device__ __forceinline__ void split_store8(uint32_t* dsth, uint32_t* dstl,
                                             float4 f0, float4 f4) {
    float a[8] = {f0.x, f4.x, f0.y, f4.y, f0.z, f4.z, f0.w, f4.w};
    uint32_t hi[8], lo[8];
#pragma unroll
    for (int j = 0; j < 8; j++) {
        hi[j] = f2tf32(a[j]);
        lo[j] = f2tf32(a[j] - __uint_as_float(hi[j]));
    }
    *(uint4*)&dsth[0] = make_uint4(hi[0], hi[1], hi[2], hi[3]);
    *(uint4*)&dsth[4] = make_uint4(hi[4], hi[5], hi[6], hi[7]);
    *(uint4*)&dstl[0] = make_uint4(lo[0], lo[1], lo[2], lo[3]);
    *(uint4*)&dstl[4] = make_uint4(lo[4], lo[5], lo[6], lo[7]);
}

__global__ __launch_bounds__(256) void proj_tc_kernel(
    const float* __restrict__ x,
    const float* __restrict__ Wq,
    const float* __restrict__ Wk,
    const float* __restrict__ Wv)
{
    __shared__ __align__(16) uint32_t xh[128][PADK];
    __shared__ __align__(16) uint32_t xl[128][PADK];
    __shared__ __align__(16) uint32_t wh[192][PADK];
    __shared__ __align__(16) uint32_t wl[192][PADK];

    const int m0   = blockIdx.x * 128;
    const int tid  = threadIdx.x;
    const int warp = tid >> 5;
    const int lane = tid & 31;
    const int grp  = lane >> 2;   // 0..7
    const int tig  = lane & 3;    // 0..3

    // per-thread source pointers (fixed rows, advance by 8 floats per chunk)
    const float* src0 = nullptr;
    const float* src1 = nullptr;
    int wrow0 = -1, wrow1 = -1;
    if (tid < 128) {
        src0 = &x[(size_t)(m0 + tid) * C_SZ];
    } else {
        int rt = tid - 128;
        wrow0 = rt;            // 0..127
        wrow1 = rt + 96;       // 96..223, valid if <192
        {
            int row = wrow0;
            src0 = (row < 64) ? &Wq[(size_t)row * C_SZ]
                 : (row < 128) ? &Wk[(size_t)(row - 64) * C_SZ]
                 : &Wv[(size_t)(row - 128) * C_SZ];
        }
        if (wrow1 < 192) {
            int row = wrow1;
            src1 = (row < 64) ? &Wq[(size_t)row * C_SZ]
                 : (row < 128) ? &Wk[(size_t)(row - 64) * C_SZ]
                 : &Wv[(size_t)(row - 128) * C_SZ];
        }
    }

    float acc[24][4];
#pragma unroll
    for (int nt = 0; nt < 24; nt++)
#pragma unroll
        for (int j = 0; j < 4; j++) acc[nt][j] = 0.f;

    // prefetch chunk 0
    float4 p00, p04, p10, p14;
    p00 = *(const float4*)src0;
    p04 = *(const float4*)(src0 + 4);
    if (src1) { p10 = *(const float4*)src1; p14 = *(const float4*)(src1 + 4); }

    for (int k0 = 0; k0 < C_SZ; k0 += KC) {
        // ---- convert + store prefetched chunk ----
        if (tid < 128) {
            split_store8(&xh[tid][0], &xl[tid][0], p00, p04);
        } else {
            split_store8(&wh[wrow0][0], &wl[wrow0][0], p00, p04);
            if (src1) split_store8(&wh[wrow1][0], &wl[wrow1][0], p10, p14);
        }
        __syncthreads();

        // ---- issue next chunk's loads (overlap with MMA below) ----
        if (k0 + KC < C_SZ) {
            const float* s0 = src0 + k0 + KC;
            p00 = *(const float4*)s0;
            p04 = *(const float4*)(s0 + 4);
            if (src1) {
                const float* s1 = src1 + k0 + KC;
                p10 = *(const float4*)s1;
                p14 = *(const float4*)(s1 + 4);
            }
        }

        // ---- fragments + MMA ----
        const int mw = warp * 16;
        uint32_t ah[4], al[4];
        {
            uint2 q0 = *(const uint2*)&xh[mw + grp][tig * 2];      // (k, k+4)
            uint2 q1 = *(const uint2*)&xh[mw + grp + 8][tig * 2];
            ah[0] = q0.x; ah[2] = q0.y; ah[1] = q1.x; ah[3] = q1.y;
            uint2 s0 = *(const uint2*)&xl[mw + grp][tig * 2];
            uint2 s1 = *(const uint2*)&xl[mw + grp + 8][tig * 2];
            al[0] = s0.x; al[2] = s0.y; al[1] = s1.x; al[3] = s1.y;
        }
#pragma unroll
        for (int nt = 0; nt < 24; nt++) {
            const int wrow = nt * 8 + grp;
            uint2 bh2 = *(const uint2*)&wh[wrow][tig * 2];
            uint2 bl2 = *(const uint2*)&wl[wrow][tig * 2];
            uint32_t bh[2] = {bh2.x, bh2.y};
            uint32_t bl[2] = {bl2.x, bl2.y};
            mma_tf32(acc[nt], al, bh);   // lo*hi
            mma_tf32(acc[nt], ah, bl);   // hi*lo
            mma_tf32(acc[nt], ah, bh);   // hi*hi
        }
        __syncthreads();
    }

    // epilogue (identical to verified round-4 mapping)
    const int mw = m0 + warp * 16;
#pragma unroll
    for (int nt = 0; nt < 24; nt++) {
        float* out = (nt < 8) ? g_Q : (nt < 16) ? g_K : g_V;
        int col = (nt & 7) * 8 + tig * 2;
        float2 v01 = make_float2(acc[nt][0], acc[nt][1]);
        float2 v23 = make_float2(acc[nt][2], acc[nt][3]);
        *(float2*)&out[(size_t)(mw + grp) * H_SZ + col]     = v01;
        *(float2*)&out[(size_t)(mw + grp + 8) * H_SZ + col] = v23;
    }
}

// ---------------------------------------------------------------------------
// Sparse BigBird attention, 4 QUERY ROWS PER BLOCK.
// Rows r0..r0+3 share one union column list:
//   global  [0, gn)          gn = min(64, r3+1)
//   local   [max(64,lo0), r3] (cols <64 already in global part)
//   random  64 <= c < lo0, deduped via bitmap (others are covered above)
// Per-(row,col) validity re-derived exactly as the reference mask:
//   (c<=ri) && (c>ri-64 || c<64 || random-bit(ri,c))      [rows<64 is
//   subsumed by c<64 under causality]
// Scores stored sc[col][4] so softmax + V passes use float4 accesses.
// All __shfl_xor_sync sit in warp-uniform control flow.
// ---------------------------------------------------------------------------
#define QR 4
#define MAXC 392

__global__ __launch_bounds__(256) void attn4_kernel(
    const int* __restrict__ random_cols,
    float* __restrict__ out)
{
    const int blk = blockIdx.x;            // 0 .. 4095
    const int b   = blk >> 9;              // 512 blocks per batch
    const int r0  = (blk & 511) * QR;
    const int r3  = r0 + 3;

    __shared__ int   cols[MAXC];
    __shared__ __align__(16) float sc[MAXC][4];
    __shared__ __align__(16) float qs[QR][H_SZ];
    __shared__ uint32_t rbit[QR][64];
    __shared__ uint32_t ubit[64];
    __shared__ int   s_n;
    __shared__ __align__(16) float4 red4[8];
    __shared__ float4 s_mx4, s_inv4;
    __shared__ __align__(16) float outp[16][256];   // [group][row*64+dim]

    const int tid  = threadIdx.x;
    const int lane = tid & 31;
    const int warp = tid >> 5;
    const int i4   = tid >> 6;    // 0..3  (row for setup)
    const int j4   = tid & 63;    // 0..63

    // ---- phase 0: init + loads ----
    rbit[i4][j4] = 0;                          // 256 words exactly
    if (tid < 64) ubit[tid] = 0;
    if (tid == 0) s_n = 0;
    const int myrnd = random_cols[(r0 + i4) * NRAND + j4];
    qs[i4][j4] = g_Q[((size_t)b * T_SZ + r0 + i4) * H_SZ + j4];

    const int lo0 = max(0, r0 - (WIN - 1));
    const int gn  = min(NGLOB, r3 + 1);
    const int l0u = max(64, lo0);
    const int ln  = max(0, r3 - l0u + 1);
    __syncthreads();

    // ---- phase 1: bitmaps + union list ----
    atomicOr(&rbit[i4][myrnd >> 5], 1u << (myrnd & 31));
    if (tid < gn) cols[tid] = tid;
    if (tid >= 64 && tid < 64 + ln) cols[gn + tid - 64] = l0u + (tid - 64);
    if (myrnd >= 64 && myrnd < lo0) {          // only range not covered above
        uint32_t bit = 1u << (myrnd & 31);
        uint32_t old = atomicOr(&ubit[myrnd >> 5], bit);
        if (!(old & bit)) {
            int p = atomicAdd(&s_n, 1);
            cols[gn + ln + p] = myrnd;
        }
    }
    __syncthreads();
    const int n = gn + ln + s_n;               // <= 64+67+256 < MAXC

    // ---- score pass: 8-lane groups, 4 dots per K load ----
    const int l8 = lane & 7;
    const int g8 = lane >> 3;
    float4 qA[QR], qB[QR];
#pragma unroll
    for (int i = 0; i < QR; i++) {
        qA[i] = *(const float4*)&qs[i][l8 * 8];
        qB[i] = *(const float4*)&qs[i][l8 * 8 + 4];
    }
    const size_t bbase = (size_t)b * T_SZ;

    for (int ci0 = warp * 4; ci0 < n; ci0 += 32) {     // warp-uniform bound
        const int  ci  = ci0 + g8;
        const bool act = (ci < n);
        const int  c   = cols[act ? ci : 0];
        const float* kp = &g_K[(bbase + c) * H_SZ + l8 * 8];
        float4 ka = *(const float4*)kp;
        float4 kb = *(const float4*)(kp + 4);
        float p0 = qA[0].x*ka.x + qA[0].y*ka.y + qA[0].z*ka.z + qA[0].w*ka.w
                 + qB[0].x*kb.x + qB[0].y*kb.y + qB[0].z*kb.z + qB[0].w*kb.w;
        float p1 = qA[1].x*ka.x + qA[1].y*ka.y + qA[1].z*ka.z + qA[1].w*ka.w
                 + qB[1].x*kb.x + qB[1].y*kb.y + qB[1].z*kb.z + qB[1].w*kb.w;
        float p2 = qA[2].x*ka.x + qA[2].y*ka.y + qA[2].z*ka.z + qA[2].w*ka.w
                 + qB[2].x*kb.x + qB[2].y*kb.y + qB[2].z*kb.z + qB[2].w*kb.w;
        float p3 = qA[3].x*ka.x + qA[3].y*ka.y + qA[3].z*ka.z + qA[3].w*ka.w
                 + qB[3].x*kb.x + qB[3].y*kb.y + qB[3].z*kb.z + qB[3].w*kb.w;
#pragma unroll
        for (int o = 4; o; o >>= 1) {
            p0 += __shfl_xor_sync(0xffffffffu, p0, o);
            p1 += __shfl_xor_sync(0xffffffffu, p1, o);
            p2 += __shfl_xor_sync(0xffffffffu, p2, o);
            p3 += __shfl_xor_sync(0xffffffffu, p3, o);
        }
        if (act && l8 < QR) {
            const int ri = r0 + l8;
            float pv = (l8 == 0) ? p0 : (l8 == 1) ? p1 : (l8 == 2) ? p2 : p3;
            bool allowed = (c <= ri) &&
                           ((c > ri - WIN) || (c < NGLOB) ||
                            ((rbit[l8][c >> 5] >> (c & 31)) & 1u));
            sc[ci][l8] = allowed ? pv * 0.125f : -INFINITY;
        }
    }
    __syncthreads();

    // ---- softmax pass 1: componentwise max over 4 rows ----
    float4 m4 = make_float4(-1e30f, -1e30f, -1e30f, -1e30f);
    for (int ci = tid; ci < n; ci += 256) {
        float4 s4 = *(const float4*)&sc[ci][0];
        m4.x = fmaxf(m4.x, s4.x); m4.y = fmaxf(m4.y, s4.y);
        m4.z = fmaxf(m4.z, s4.z); m4.w = fmaxf(m4.w, s4.w);
    }
#pragma unroll
    for (int o = 16; o; o >>= 1) {
        m4.x = fmaxf(m4.x, __shfl_xor_sync(0xffffffffu, m4.x, o));
        m4.y = fmaxf(m4.y, __shfl_xor_sync(0xffffffffu, m4.y, o));
        m4.z = fmaxf(m4.z, __shfl_xor_sync(0xffffffffu, m4.z, o));
        m4.w = fmaxf(m4.w, __shfl_xor_sync(0xffffffffu, m4.w, o));
    }
    if (lane == 0) red4[warp] = m4;
    __syncthreads();
    if (tid == 0) {
        float4 m = red4[0];
#pragma unroll
        for (int w = 1; w < 8; w++) {
            m.x = fmaxf(m.x, red4[w].x); m.y = fmaxf(m.y, red4[w].y);
            m.z = fmaxf(m.z, red4[w].z); m.w = fmaxf(m.w, red4[w].w);
        }
        s_mx4 = m;
    }
    __syncthreads();
    const float4 mx = s_mx4;

    // ---- softmax pass 2: exp + sum ----
    float4 sum4 = make_float4(0.f, 0.f, 0.f, 0.f);
    for (int ci = tid; ci < n; ci += 256) {
        float4 s4 = *(const float4*)&sc[ci][0];
        s4.x = __expf(s4.x - mx.x); s4.y = __expf(s4.y - mx.y);
        s4.z = __expf(s4.z - mx.z); s4.w = __expf(s4.w - mx.w);
        *(float4*)&sc[ci][0] = s4;
        sum4.x += s4.x; sum4.y += s4.y; sum4.z += s4.z; sum4.w += s4.w;
    }
#pragma unroll
    for (int o = 16; o; o >>= 1) {
        sum4.x += __shfl_xor_sync(0xffffffffu, sum4.x, o);
        sum4.y += __shfl_xor_sync(0xffffffffu, sum4.y, o);
        sum4.z += __shfl_xor_sync(0xffffffffu, sum4.z, o);
        sum4.w += __shfl_xor_sync(0xffffffffu, sum4.w, o);
    }
    if (lane == 0) red4[warp] = sum4;
    __syncthreads();
    if (tid == 0) {
        float4 s = red4[0];
#pragma unroll
        for (int w = 1; w < 8; w++) {
            s.x += red4[w].x; s.y += red4[w].y;
            s.z += red4[w].z; s.w += red4[w].w;
        }
        s_inv4 = make_float4(1.f/s.x, 1.f/s.y, 1.f/s.z, 1.f/s.w);
    }
    __syncthreads();

    // ---- V pass: 16 groups of 16 threads; one V load feeds 4 rows ----
    const int dg = tid & 15;
    const int gq = tid >> 4;
    float4 a0 = make_float4(0,0,0,0), a1 = a0, a2 = a0, a3 = a0;
    for (int ci = gq; ci < n; ci += 16) {
        float4 w4 = *(const float4*)&sc[ci][0];
        float4 v  = *(const float4*)&g_V[(bbase + cols[ci]) * H_SZ + dg * 4];
        a0.x += w4.x*v.x; a0.y += w4.x*v.y; a0.z += w4.x*v.z; a0.w += w4.x*v.w;
        a1.x += w4.y*v.x; a1.y += w4.y*v.y; a1.z += w4.y*v.z; a1.w += w4.y*v.w;
        a2.x += w4.z*v.x; a2.y += w4.z*v.y; a2.z += w4.z*v.z; a2.w += w4.z*v.w;
        a3.x += w4.w*v.x; a3.y += w4.w*v.y; a3.z += w4.w*v.z; a3.w += w4.w*v.w;
    }
    *(float4*)&outp[gq][0 * 64 + dg * 4] = a0;
    *(float4*)&outp[gq][1 * 64 + dg * 4] = a1;
    *(float4*)&outp[gq][2 * 64 + dg * 4] = a2;
    *(float4*)&outp[gq][3 * 64 + dg * 4] = a3;
    __syncthreads();

    // ---- final reduce + normalize ----
    {
        const int i = tid >> 6;
        const int d = tid & 63;
        float o = 0.f;
#pragma unroll
        for (int g2 = 0; g2 < 16; g2++) o += outp[g2][i * 64 + d];
        float inv = (i == 0) ? s_inv4.x : (i == 1) ? s_inv4.y
                  : (i == 2) ? s_inv4.z : s_inv4.w;
        out[((size_t)b * T_SZ + r0 + i) * H_SZ + d] = o * inv;
    }
}

// ---------------------------------------------------------------------------
// kernel_launch — inputs per metadata order: x, random_cols, Wk, Wq, Wv
// ---------------------------------------------------------------------------
extern "C" void kernel_launch(void* const* d_in, const int* in_sizes, int n_in,
                              void* d_out, int out_size)
{
    const float* x           = (const float*)d_in[0];
    const int*   random_cols = (const int*)  d_in[1];
    const float* Wk          = (const float*)d_in[2];
    const float* Wq          = (const float*)d_in[3];
    const float* Wv          = (const float*)d_in[4];
    float* out = (float*)d_out;

    proj_tc_kernel<<<BT / 128, 256>>>(x, Wq, Wk, Wv);

    attn4_kernel<<<BT / QR, 256>>>(random_cols, out);
}

// round 6
// speedup vs baseline: 1.6546x; 1.2695x over previous
#include <cuda_runtime.h>
#include <cuda_bf16.h>
#include <math.h>
#include <stdint.h>

// Problem constants
#define B_SZ 8
#define T_SZ 2048
#define C_SZ 1024
#define H_SZ 64
#define WIN 64
#define NGLOB 64
#define NRAND 64

#define BT (B_SZ * T_SZ)          // 16384 rows

// Scratch for projected q, k, v  (4 MB each) — device globals, no allocation.
__device__ float g_Q[BT * H_SZ];
__device__ float g_K[BT * H_SZ];
__device__ float g_V[BT * H_SZ];

// ---------------------------------------------------------------------------
// bf16 helpers
// ---------------------------------------------------------------------------
__device__ __forceinline__ uint32_t pack_bf16(__nv_bfloat16 a, __nv_bfloat16 b) {
    // low half = a, high half = b
    return (uint32_t)__bfloat16_as_ushort(a) | ((uint32_t)__bfloat16_as_ushort(b) << 16);
}

__device__ __forceinline__ void mma_bf16(float* c, const uint32_t* a, const uint32_t* b) {
    asm volatile(
        "mma.sync.aligned.m16n8k16.row.col.f32.bf16.bf16.f32 "
        "{%0,%1,%2,%3}, {%4,%5,%6,%7}, {%8,%9}, {%0,%1,%2,%3};"
        : "+f"(c[0]), "+f"(c[1]), "+f"(c[2]), "+f"(c[3])
        : "r"(a[0]), "r"(a[1]), "r"(a[2]), "r"(a[3]),
          "r"(b[0]), "r"(b[1]));
}

// ---------------------------------------------------------------------------
// FUSED projection GEMM (Q,K,V) via 3x BF16-split mma.sync.m16n8k16:
//   out[m][h] = sum_c x[m][c] * W[h][c],  M=16384, K=1024, N=3x64
// x = hi + lo in bf16; acc += hi*hi + lo*hi + hi*lo (fp32 accumulate);
// dropped lo*lo term ~2^-18 relative -> well under tolerance.
//
// Block tile: 64(M) x 192(N) x 16(K). 256 CTAs -> 2 CTAs/SM (overlap).
// 8 warps: warp&3 = m-tile (16 rows), warp>>2 = n-half (12 of 24 n-tiles).
// smem word = bf16x2 (2 K-values). Per row 8 words stored PAIR-PERMUTED
// [w0,w4,w1,w5,w2,w6,w3,w7] so fragment pair (w_tig, w_tig+4) is adjacent
// -> all fragment loads are LDS.64. Row stride 12 words.
// ---------------------------------------------------------------------------
#define KC 16
#define PADK 12

__device__ __forceinline__ void split_store16(uint32_t* dsth, uint32_t* dstl,
                                              const float4* f4) {
    const float* f = (const float*)f4;   // 16 floats
    uint32_t hw[8], lw[8];
#pragma unroll
    for (int j = 0; j < 8; j++) {
        float a = f[2 * j], b = f[2 * j + 1];
        __nv_bfloat16 ha = __float2bfloat16_rn(a);
        __nv_bfloat16 hb = __float2bfloat16_rn(b);
        __nv_bfloat16 la = __float2bfloat16_rn(a - __bfloat162float(ha));
        __nv_bfloat16 lb = __float2bfloat16_rn(b - __bfloat162float(hb));
        hw[j] = pack_bf16(ha, hb);
        lw[j] = pack_bf16(la, lb);
    }
    // permuted: position 2t = word t, position 2t+1 = word t+4
    *(uint4*)&dsth[0] = make_uint4(hw[0], hw[4], hw[1], hw[5]);
    *(uint4*)&dsth[4] = make_uint4(hw[2], hw[6], hw[3], hw[7]);
    *(uint4*)&dstl[0] = make_uint4(lw[0], lw[4], lw[1], lw[5]);
    *(uint4*)&dstl[4] = make_uint4(lw[2], lw[6], lw[3], lw[7]);
}

__global__ __launch_bounds__(256, 2) void proj_tc_kernel(
    const float* __restrict__ x,
    const float* __restrict__ Wq,
    const float* __restrict__ Wk,
    const float* __restrict__ Wv)
{
    __shared__ __align__(16) uint32_t xh[64][PADK];
    __shared__ __align__(16) uint32_t xl[64][PADK];
    __shared__ __align__(16) uint32_t wh[192][PADK];
    __shared__ __align__(16) uint32_t wl[192][PADK];

    const int m0   = blockIdx.x * 64;
    const int tid  = threadIdx.x;
    const int warp = tid >> 5;
    const int lane = tid & 31;
    const int grp  = lane >> 2;   // 0..7
    const int tig  = lane & 3;    // 0..3

    // one smem row per thread: tid<64 -> x row, else W row (0..191)
    const float* src;
    uint32_t *dh, *dl;
    if (tid < 64) {
        src = &x[(size_t)(m0 + tid) * C_SZ];
        dh = &xh[tid][0]; dl = &xl[tid][0];
    } else {
        const int row = tid - 64;
        src = (row < 64)  ? &Wq[(size_t)row * C_SZ]
            : (row < 128) ? &Wk[(size_t)(row - 64) * C_SZ]
                          : &Wv[(size_t)(row - 128) * C_SZ];
        dh = &wh[row][0]; dl = &wl[row][0];
    }

    float acc[12][4];
#pragma unroll
    for (int nt = 0; nt < 12; nt++)
#pragma unroll
        for (int j = 0; j < 4; j++) acc[nt][j] = 0.f;

    // prefetch chunk 0 (16 floats)
    float4 pf[4];
#pragma unroll
    for (int j = 0; j < 4; j++) pf[j] = *(const float4*)(src + j * 4);

    const int mt = warp & 3;       // m-tile
    const int nh = warp >> 2;      // n-half
    const int mrow = mt * 16 + grp;

    for (int k0 = 0; k0 < C_SZ; k0 += KC) {
        // convert + store the prefetched chunk
        split_store16(dh, dl, pf);
        __syncthreads();

        // issue next chunk's loads (overlap with MMA phase)
        if (k0 + KC < C_SZ) {
            const float* s = src + k0 + KC;
#pragma unroll
            for (int j = 0; j < 4; j++) pf[j] = *(const float4*)(s + j * 4);
        }

        // fragments + MMA
        uint32_t ah[4], al[4];
        {
            uint2 q0 = *(const uint2*)&xh[mrow][tig * 2];       // (w_tig, w_tig+4)
            uint2 q1 = *(const uint2*)&xh[mrow + 8][tig * 2];
            ah[0] = q0.x; ah[2] = q0.y; ah[1] = q1.x; ah[3] = q1.y;
            uint2 s0 = *(const uint2*)&xl[mrow][tig * 2];
            uint2 s1 = *(const uint2*)&xl[mrow + 8][tig * 2];
            al[0] = s0.x; al[2] = s0.y; al[1] = s1.x; al[3] = s1.y;
        }
#pragma unroll
        for (int i = 0; i < 12; i++) {
            const int wrow = (nh * 12 + i) * 8 + grp;
            uint2 bh2 = *(const uint2*)&wh[wrow][tig * 2];
            uint2 bl2 = *(const uint2*)&wl[wrow][tig * 2];
            uint32_t bh[2] = {bh2.x, bh2.y};
            uint32_t bl[2] = {bl2.x, bl2.y};
            mma_bf16(acc[i], al, bh);   // lo*hi
            mma_bf16(acc[i], ah, bl);   // hi*lo
            mma_bf16(acc[i], ah, bh);   // hi*hi
        }
        __syncthreads();
    }

    // epilogue: c0=(grp, 2tig), c1=(grp, 2tig+1), c2=(grp+8, 2tig), c3=+1
    const int mwr = m0 + mt * 16 + grp;
#pragma unroll
    for (int i = 0; i < 12; i++) {
        const int ntg = nh * 12 + i;
        float* out = (ntg < 8) ? g_Q : (ntg < 16) ? g_K : g_V;
        const int col = (ntg & 7) * 8 + tig * 2;
        *(float2*)&out[(size_t)mwr * H_SZ + col]       = make_float2(acc[i][0], acc[i][1]);
        *(float2*)&out[(size_t)(mwr + 8) * H_SZ + col] = make_float2(acc[i][2], acc[i][3]);
    }
}

// ---------------------------------------------------------------------------
// Sparse BigBird attention, 4 query rows per block (UNCHANGED, passing).
// ---------------------------------------------------------------------------
#define QR 4
#define MAXC 392

__global__ __launch_bounds__(256) void attn4_kernel(
    const int* __restrict__ random_cols,
    float* __restrict__ out)
{
    const int blk = blockIdx.x;            // 0 .. 4095
    const int b   = blk >> 9;              // 512 blocks per batch
    const int r0  = (blk & 511) * QR;
    const int r3  = r0 + 3;

    __shared__ int   cols[MAXC];
    __shared__ __align__(16) float sc[MAXC][4];
    __shared__ __align__(16) float qs[QR][H_SZ];
    __shared__ uint32_t rbit[QR][64];
    __shared__ uint32_t ubit[64];
    __shared__ int   s_n;
    __shared__ __align__(16) float4 red4[8];
    __shared__ float4 s_mx4, s_inv4;
    __shared__ __align__(16) float outp[16][256];   // [group][row*64+dim]

    const int tid  = threadIdx.x;
    const int lane = tid & 31;
    const int warp = tid >> 5;
    const int i4   = tid >> 6;    // 0..3  (row for setup)
    const int j4   = tid & 63;    // 0..63

    // ---- phase 0: init + loads ----
    rbit[i4][j4] = 0;                          // 256 words exactly
    if (tid < 64) ubit[tid] = 0;
    if (tid == 0) s_n = 0;
    const int myrnd = random_cols[(r0 + i4) * NRAND + j4];
    qs[i4][j4] = g_Q[((size_t)b * T_SZ + r0 + i4) * H_SZ + j4];

    const int lo0 = max(0, r0 - (WIN - 1));
    const int gn  = min(NGLOB, r3 + 1);
    const int l0u = max(64, lo0);
    const int ln  = max(0, r3 - l0u + 1);
    __syncthreads();

    // ---- phase 1: bitmaps + union list ----
    atomicOr(&rbit[i4][myrnd >> 5], 1u << (myrnd & 31));
    if (tid < gn) cols[tid] = tid;
    if (tid >= 64 && tid < 64 + ln) cols[gn + tid - 64] = l0u + (tid - 64);
    if (myrnd >= 64 && myrnd < lo0) {          // only range not covered above
        uint32_t bit = 1u << (myrnd & 31);
        uint32_t old = atomicOr(&ubit[myrnd >> 5], bit);
        if (!(old & bit)) {
            int p = atomicAdd(&s_n, 1);
            cols[gn + ln + p] = myrnd;
        }
    }
    __syncthreads();
    const int n = gn + ln + s_n;

    // ---- score pass: 8-lane groups, 4 dots per K load ----
    const int l8 = lane & 7;
    const int g8 = lane >> 3;
    float4 qA[QR], qB[QR];
#pragma unroll
    for (int i = 0; i < QR; i++) {
        qA[i] = *(const float4*)&qs[i][l8 * 8];
        qB[i] = *(const float4*)&qs[i][l8 * 8 + 4];
    }
    const size_t bbase = (size_t)b * T_SZ;

    for (int ci0 = warp * 4; ci0 < n; ci0 += 32) {     // warp-uniform bound
        const int  ci  = ci0 + g8;
        const bool act = (ci < n);
        const int  c   = cols[act ? ci : 0];
        const float* kp = &g_K[(bbase + c) * H_SZ + l8 * 8];
        float4 ka = *(const float4*)kp;
        float4 kb = *(const float4*)(kp + 4);
        float p0 = qA[0].x*ka.x + qA[0].y*ka.y + qA[0].z*ka.z + qA[0].w*ka.w
                 + qB[0].x*kb.x + qB[0].y*kb.y + qB[0].z*kb.z + qB[0].w*kb.w;
        float p1 = qA[1].x*ka.x + qA[1].y*ka.y + qA[1].z*ka.z + qA[1].w*ka.w
                 + qB[1].x*kb.x + qB[1].y*kb.y + qB[1].z*kb.z + qB[1].w*kb.w;
        float p2 = qA[2].x*ka.x + qA[2].y*ka.y + qA[2].z*ka.z + qA[2].w*ka.w
                 + qB[2].x*kb.x + qB[2].y*kb.y + qB[2].z*kb.z + qB[2].w*kb.w;
        float p3 = qA[3].x*ka.x + qA[3].y*ka.y + qA[3].z*ka.z + qA[3].w*ka.w
                 + qB[3].x*kb.x + qB[3].y*kb.y + qB[3].z*kb.z + qB[3].w*kb.w;
#pragma unroll
        for (int o = 4; o; o >>= 1) {
            p0 += __shfl_xor_sync(0xffffffffu, p0, o);
            p1 += __shfl_xor_sync(0xffffffffu, p1, o);
            p2 += __shfl_xor_sync(0xffffffffu, p2, o);
            p3 += __shfl_xor_sync(0xffffffffu, p3, o);
        }
        if (act && l8 < QR) {
            const int ri = r0 + l8;
            float pv = (l8 == 0) ? p0 : (l8 == 1) ? p1 : (l8 == 2) ? p2 : p3;
            bool allowed = (c <= ri) &&
                           ((c > ri - WIN) || (c < NGLOB) ||
                            ((rbit[l8][c >> 5] >> (c & 31)) & 1u));
            sc[ci][l8] = allowed ? pv * 0.125f : -INFINITY;
        }
    }
    __syncthreads();

    // ---- softmax pass 1: componentwise max over 4 rows ----
    float4 m4 = make_float4(-1e30f, -1e30f, -1e30f, -1e30f);
    for (int ci = tid; ci < n; ci += 256) {
        float4 s4 = *(const float4*)&sc[ci][0];
        m4.x = fmaxf(m4.x, s4.x); m4.y = fmaxf(m4.y, s4.y);
        m4.z = fmaxf(m4.z, s4.z); m4.w = fmaxf(m4.w, s4.w);
    }
#pragma unroll
    for (int o = 16; o; o >>= 1) {
        m4.x = fmaxf(m4.x, __shfl_xor_sync(0xffffffffu, m4.x, o));
        m4.y = fmaxf(m4.y, __shfl_xor_sync(0xffffffffu, m4.y, o));
        m4.z = fmaxf(m4.z, __shfl_xor_sync(0xffffffffu, m4.z, o));
        m4.w = fmaxf(m4.w, __shfl_xor_sync(0xffffffffu, m4.w, o));
    }
    if (lane == 0) red4[warp] = m4;
    __syncthreads();
    if (tid == 0) {
        float4 m = red4[0];
#pragma unroll
        for (int w = 1; w < 8; w++) {
            m.x = fmaxf(m.x, red4[w].x); m.y = fmaxf(m.y, red4[w].y);
            m.z = fmaxf(m.z, red4[w].z); m.w = fmaxf(m.w, red4[w].w);
        }
        s_mx4 = m;
    }
    __syncthreads();
    const float4 mx = s_mx4;

    // ---- softmax pass 2: exp + sum ----
    float4 sum4 = make_float4(0.f, 0.f, 0.f, 0.f);
    for (int ci = tid; ci < n; ci += 256) {
        float4 s4 = *(const float4*)&sc[ci][0];
        s4.x = __expf(s4.x - mx.x); s4.y = __expf(s4.y - mx.y);
        s4.z = __expf(s4.z - mx.z); s4.w = __expf(s4.w - mx.w);
        *(float4*)&sc[ci][0] = s4;
        sum4.x += s4.x; sum4.y += s4.y; sum4.z += s4.z; sum4.w += s4.w;
    }
#pragma unroll
    for (int o = 16; o; o >>= 1) {
        sum4.x += __shfl_xor_sync(0xffffffffu, sum4.x, o);
        sum4.y += __shfl_xor_sync(0xffffffffu, sum4.y, o);
        sum4.z += __shfl_xor_sync(0xffffffffu, sum4.z, o);
        sum4.w += __shfl_xor_sync(0xffffffffu, sum4.w, o);
    }
    if (lane == 0) red4[warp] = sum4;
    __syncthreads();
    if (tid == 0) {
        float4 s = red4[0];
#pragma unroll
        for (int w = 1; w < 8; w++) {
            s.x += red4[w].x; s.y += red4[w].y;
            s.z += red4[w].z; s.w += red4[w].w;
        }
        s_inv4 = make_float4(1.f/s.x, 1.f/s.y, 1.f/s.z, 1.f/s.w);
    }
    __syncthreads();

    // ---- V pass: 16 groups of 16 threads; one V load feeds 4 rows ----
    const int dg = tid & 15;
    const int gq = tid >> 4;
    float4 a0 = make_float4(0,0,0,0), a1 = a0, a2 = a0, a3 = a0;
    for (int ci = gq; ci < n; ci += 16) {
        float4 w4 = *(const float4*)&sc[ci][0];
        float4 v  = *(const float4*)&g_V[(bbase + cols[ci]) * H_SZ + dg * 4];
        a0.x += w4.x*v.x; a0.y += w4.x*v.y; a0.z += w4.x*v.z; a0.w += w4.x*v.w;
        a1.x += w4.y*v.x; a1.y += w4.y*v.y; a1.z += w4.y*v.z; a1.w += w4.y*v.w;
        a2.x += w4.z*v.x; a2.y += w4.z*v.y; a2.z += w4.z*v.z; a2.w += w4.z*v.w;
        a3.x += w4.w*v.x; a3.y += w4.w*v.y; a3.z += w4.w*v.z; a3.w += w4.w*v.w;
    }
    *(float4*)&outp[gq][0 * 64 + dg * 4] = a0;
    *(float4*)&outp[gq][1 * 64 + dg * 4] = a1;
    *(float4*)&outp[gq][2 * 64 + dg * 4] = a2;
    *(float4*)&outp[gq][3 * 64 + dg * 4] = a3;
    __syncthreads();

    // ---- final reduce + normalize ----
    {
        const int i = tid >> 6;
        const int d = tid & 63;
        float o = 0.f;
#pragma unroll
        for (int g2 = 0; g2 < 16; g2++) o += outp[g2][i * 64 + d];
        float inv = (i == 0) ? s_inv4.x : (i == 1) ? s_inv4.y
                  : (i == 2) ? s_inv4.z : s_inv4.w;
        out[((size_t)b * T_SZ + r0 + i) * H_SZ + d] = o * inv;
    }
}

// ---------------------------------------------------------------------------
// kernel_launch — inputs per metadata order: x, random_cols, Wk, Wq, Wv
// ---------------------------------------------------------------------------
extern "C" void kernel_launch(void* const* d_in, const int* in_sizes, int n_in,
                              void* d_out, int out_size)
{
    const float* x           = (const float*)d_in[0];
    const int*   random_cols = (const int*)  d_in[1];
    const float* Wk          = (const float*)d_in[2];
    const float* Wq          = (const float*)d_in[3];
    const float* Wv          = (const float*)d_in[4];
    float* out = (float*)d_out;

    proj_tc_kernel<<<BT / 64, 256>>>(x, Wq, Wk, Wv);

    attn4_kernel<<<BT / QR, 256>>>(random_cols, out);
}

// round 7
// speedup vs baseline: 2.0191x; 1.2203x over previous
#include <cuda_runtime.h>
#include <cuda_bf16.h>
#include <math.h>
#include <stdint.h>

// Problem constants
#define B_SZ 8
#define T_SZ 2048
#define C_SZ 1024
#define H_SZ 64
#define WIN 64
#define NGLOB 64
#define NRAND 64

#define BT (B_SZ * T_SZ)          // 16384 rows

// Scratch for projected q, k, v  (4 MB each) — device globals, no allocation.
__device__ float g_Q[BT * H_SZ];
__device__ float g_K[BT * H_SZ];
__device__ float g_V[BT * H_SZ];

__device__ __forceinline__ void mma_bf16(float* c, const uint32_t* a, const uint32_t* b) {
    asm volatile(
        "mma.sync.aligned.m16n8k16.row.col.f32.bf16.bf16.f32 "
        "{%0,%1,%2,%3}, {%4,%5,%6,%7}, {%8,%9}, {%0,%1,%2,%3};"
        : "+f"(c[0]), "+f"(c[1]), "+f"(c[2]), "+f"(c[3])
        : "r"(a[0]), "r"(a[1]), "r"(a[2]), "r"(a[3]),
          "r"(b[0]), "r"(b[1]));
}

// ---------------------------------------------------------------------------
// FUSED projection GEMM (Q,K,V) via 3x BF16-split mma.sync.m16n8k16.
//   out[m][h] = sum_c x[m][c] * W[h][c],  M=16384, K=1024, N=3x64
// Block tile 64(M) x 192(N) x 16(K), 256 CTAs (2/SM), 8 warps = 2(M) x 4(N).
//
// smem: single array, rows 0..63 = x tile, rows 64..255 = W tile (Q|K|V).
// Word = bf16x2 (2 K-values); 8 words/row stored PAIR-PERMUTED
// [w0,w4,w1,w5,w2,w6,w3,w7] so fragment pair (w_t, w_t+4) is one LDS.64.
//
// FILL IS COALESCED: thread i <-> (row = i>>3, word = i&7); a warp covers
// 4 rows x 64 contiguous bytes (nL=4 per LDG.64, vs 32 for the old
// one-row-per-thread fill). Store banks: row%4 offsets {0,12,24,4} + p(0..7)
// -> all 32 banks distinct, conflict-free.
// ---------------------------------------------------------------------------
#define KC 16
#define PADK 12

__global__ __launch_bounds__(256, 2) void proj_tc_kernel(
    const float* __restrict__ x,
    const float* __restrict__ Wq,
    const float* __restrict__ Wk,
    const float* __restrict__ Wv)
{
    __shared__ __align__(16) uint32_t sm_h[256][PADK];
    __shared__ __align__(16) uint32_t sm_l[256][PADK];

    const int m0   = blockIdx.x * 64;
    const int tid  = threadIdx.x;
    const int warp = tid >> 5;
    const int lane = tid & 31;
    const int grp  = lane >> 2;   // 0..7
    const int tig  = lane & 3;    // 0..3
    const int mh   = warp & 1;    // M half (32 rows)
    const int nq   = warp >> 1;   // N quarter (6 n-tiles)

    // ---- fill assignments: 8 float2 per thread (2 x-rows worth + 6 W) ----
    const float* srcs[8];
    int rp[8];                    // flat smem word index row*PADK + p
#pragma unroll
    for (int it = 0; it < 8; it++) {
        const int i = it * 256 + tid;       // 0..2047
        int r, w;
        const float* base;
        if (it < 2) {                       // x: i in 0..511
            r = i >> 3; w = i & 7;
            base = &x[(size_t)(m0 + r) * C_SZ];
            rp[it] = r * PADK;
        } else {                            // W: j in 0..1535
            const int j = i - 512;
            r = j >> 3; w = j & 7;
            base = (r < 64)  ? &Wq[(size_t)r * C_SZ]
                 : (r < 128) ? &Wk[(size_t)(r - 64) * C_SZ]
                             : &Wv[(size_t)(r - 128) * C_SZ];
            rp[it] = (64 + r) * PADK;
        }
        srcs[it] = base + w * 2;
        rp[it] += 2 * (w & 3) + (w >> 2);   // pair-permute position
    }

    float acc[2][6][4];
#pragma unroll
    for (int mt = 0; mt < 2; mt++)
#pragma unroll
        for (int i = 0; i < 6; i++)
#pragma unroll
            for (int j = 0; j < 4; j++) acc[mt][i][j] = 0.f;

    // prefetch chunk 0
    float2 pf[8];
#pragma unroll
    for (int it = 0; it < 8; it++) pf[it] = *(const float2*)srcs[it];

    for (int k0 = 0; k0 < C_SZ; k0 += KC) {
        // ---- convert + store prefetched chunk ----
#pragma unroll
        for (int it = 0; it < 8; it++) {
            const float a = pf[it].x, b = pf[it].y;
            __nv_bfloat162 h2 = __floats2bfloat162_rn(a, b);
            const uint32_t hu = *(const uint32_t*)&h2;
            const float ha = __uint_as_float(hu << 16);
            const float hb = __uint_as_float(hu & 0xFFFF0000u);
            __nv_bfloat162 l2 = __floats2bfloat162_rn(a - ha, b - hb);
            ((uint32_t*)sm_h)[rp[it]] = hu;
            ((uint32_t*)sm_l)[rp[it]] = *(const uint32_t*)&l2;
        }
        __syncthreads();

        // ---- prefetch next chunk (hides under MMA phase) ----
        if (k0 + KC < C_SZ) {
#pragma unroll
            for (int it = 0; it < 8; it++)
                pf[it] = *(const float2*)(srcs[it] + k0 + KC);
        }

        // ---- a-fragments (2 m16 tiles) ----
        uint32_t ah[2][4], al[2][4];
#pragma unroll
        for (int mt = 0; mt < 2; mt++) {
            const int mrow = mh * 32 + mt * 16 + grp;
            uint2 q0 = *(const uint2*)&sm_h[mrow][tig * 2];
            uint2 q1 = *(const uint2*)&sm_h[mrow + 8][tig * 2];
            ah[mt][0] = q0.x; ah[mt][2] = q0.y;
            ah[mt][1] = q1.x; ah[mt][3] = q1.y;
            uint2 s0 = *(const uint2*)&sm_l[mrow][tig * 2];
            uint2 s1 = *(const uint2*)&sm_l[mrow + 8][tig * 2];
            al[mt][0] = s0.x; al[mt][2] = s0.y;
            al[mt][1] = s1.x; al[mt][3] = s1.y;
        }

        // ---- b-fragments + MMAs (6 n-tiles, shared across both m-tiles) ----
#pragma unroll
        for (int i = 0; i < 6; i++) {
            const int wrow = 64 + (nq * 6 + i) * 8 + grp;
            uint2 bh2 = *(const uint2*)&sm_h[wrow][tig * 2];
            uint2 bl2 = *(const uint2*)&sm_l[wrow][tig * 2];
            uint32_t bh[2] = {bh2.x, bh2.y};
            uint32_t bl[2] = {bl2.x, bl2.y};
#pragma unroll
            for (int mt = 0; mt < 2; mt++) {
                mma_bf16(acc[mt][i], al[mt], bh);   // lo*hi
                mma_bf16(acc[mt][i], ah[mt], bl);   // hi*lo
                mma_bf16(acc[mt][i], ah[mt], bh);   // hi*hi
            }
        }
        __syncthreads();
    }

    // ---- epilogue: c0=(grp,2tig), c1=+1, c2=(grp+8,2tig), c3=+1 ----
#pragma unroll
    for (int mt = 0; mt < 2; mt++) {
        const int mwr = m0 + mh * 32 + mt * 16 + grp;
#pragma unroll
        for (int i = 0; i < 6; i++) {
            const int ntg = nq * 6 + i;
            float* out = (ntg < 8) ? g_Q : (ntg < 16) ? g_K : g_V;
            const int col = (ntg & 7) * 8 + tig * 2;
            *(float2*)&out[(size_t)mwr * H_SZ + col] =
                make_float2(acc[mt][i][0], acc[mt][i][1]);
            *(float2*)&out[(size_t)(mwr + 8) * H_SZ + col] =
                make_float2(acc[mt][i][2], acc[mt][i][3]);
        }
    }
}

// ---------------------------------------------------------------------------
// Sparse BigBird attention, 4 query rows per block (UNCHANGED, passing).
// ---------------------------------------------------------------------------
#define QR 4
#define MAXC 392

__global__ __launch_bounds__(256) void attn4_kernel(
    const int* __restrict__ random_cols,
    float* __restrict__ out)
{
    const int blk = blockIdx.x;            // 0 .. 4095
    const int b   = blk >> 9;              // 512 blocks per batch
    const int r0  = (blk & 511) * QR;
    const int r3  = r0 + 3;

    __shared__ int   cols[MAXC];
    __shared__ __align__(16) float sc[MAXC][4];
    __shared__ __align__(16) float qs[QR][H_SZ];
    __shared__ uint32_t rbit[QR][64];
    __shared__ uint32_t ubit[64];
    __shared__ int   s_n;
    __shared__ __align__(16) float4 red4[8];
    __shared__ float4 s_mx4, s_inv4;
    __shared__ __align__(16) float outp[16][256];   // [group][row*64+dim]

    const int tid  = threadIdx.x;
    const int lane = tid & 31;
    const int warp = tid >> 5;
    const int i4   = tid >> 6;    // 0..3  (row for setup)
    const int j4   = tid & 63;    // 0..63

    // ---- phase 0: init + loads ----
    rbit[i4][j4] = 0;                          // 256 words exactly
    if (tid < 64) ubit[tid] = 0;
    if (tid == 0) s_n = 0;
    const int myrnd = random_cols[(r0 + i4) * NRAND + j4];
    qs[i4][j4] = g_Q[((size_t)b * T_SZ + r0 + i4) * H_SZ + j4];

    const int lo0 = max(0, r0 - (WIN - 1));
    const int gn  = min(NGLOB, r3 + 1);
    const int l0u = max(64, lo0);
    const int ln  = max(0, r3 - l0u + 1);
    __syncthreads();

    // ---- phase 1: bitmaps + union list ----
    atomicOr(&rbit[i4][myrnd >> 5], 1u << (myrnd & 31));
    if (tid < gn) cols[tid] = tid;
    if (tid >= 64 && tid < 64 + ln) cols[gn + tid - 64] = l0u + (tid - 64);
    if (myrnd >= 64 && myrnd < lo0) {          // only range not covered above
        uint32_t bit = 1u << (myrnd & 31);
        uint32_t old = atomicOr(&ubit[myrnd >> 5], bit);
        if (!(old & bit)) {
            int p = atomicAdd(&s_n, 1);
            cols[gn + ln + p] = myrnd;
        }
    }
    __syncthreads();
    const int n = gn + ln + s_n;

    // ---- score pass: 8-lane groups, 4 dots per K load ----
    const int l8 = lane & 7;
    const int g8 = lane >> 3;
    float4 qA[QR], qB[QR];
#pragma unroll
    for (int i = 0; i < QR; i++) {
        qA[i] = *(const float4*)&qs[i][l8 * 8];
        qB[i] = *(const float4*)&qs[i][l8 * 8 + 4];
    }
    const size_t bbase = (size_t)b * T_SZ;

    for (int ci0 = warp * 4; ci0 < n; ci0 += 32) {     // warp-uniform bound
        const int  ci  = ci0 + g8;
        const bool act = (ci < n);
        const int  c   = cols[act ? ci : 0];
        const float* kp = &g_K[(bbase + c) * H_SZ + l8 * 8];
        float4 ka = *(const float4*)kp;
        float4 kb = *(const float4*)(kp + 4);
        float p0 = qA[0].x*ka.x + qA[0].y*ka.y + qA[0].z*ka.z + qA[0].w*ka.w
                 + qB[0].x*kb.x + qB[0].y*kb.y + qB[0].z*kb.z + qB[0].w*kb.w;
        float p1 = qA[1].x*ka.x + qA[1].y*ka.y + qA[1].z*ka.z + qA[1].w*ka.w
                 + qB[1].x*kb.x + qB[1].y*kb.y + qB[1].z*kb.z + qB[1].w*kb.w;
        float p2 = qA[2].x*ka.x + qA[2].y*ka.y + qA[2].z*ka.z + qA[2].w*ka.w
                 + qB[2].x*kb.x + qB[2].y*kb.y + qB[2].z*kb.z + qB[2].w*kb.w;
        float p3 = qA[3].x*ka.x + qA[3].y*ka.y + qA[3].z*ka.z + qA[3].w*ka.w
                 + qB[3].x*kb.x + qB[3].y*kb.y + qB[3].z*kb.z + qB[3].w*kb.w;
#pragma unroll
        for (int o = 4; o; o >>= 1) {
            p0 += __shfl_xor_sync(0xffffffffu, p0, o);
            p1 += __shfl_xor_sync(0xffffffffu, p1, o);
            p2 += __shfl_xor_sync(0xffffffffu, p2, o);
            p3 += __shfl_xor_sync(0xffffffffu, p3, o);
        }
        if (act && l8 < QR) {
            const int ri = r0 + l8;
            float pv = (l8 == 0) ? p0 : (l8 == 1) ? p1 : (l8 == 2) ? p2 : p3;
            bool allowed = (c <= ri) &&
                           ((c > ri - WIN) || (c < NGLOB) ||
                            ((rbit[l8][c >> 5] >> (c & 31)) & 1u));
            sc[ci][l8] = allowed ? pv * 0.125f : -INFINITY;
        }
    }
    __syncthreads();

    // ---- softmax pass 1: componentwise max over 4 rows ----
    float4 m4 = make_float4(-1e30f, -1e30f, -1e30f, -1e30f);
    for (int ci = tid; ci < n; ci += 256) {
        float4 s4 = *(const float4*)&sc[ci][0];
        m4.x = fmaxf(m4.x, s4.x); m4.y = fmaxf(m4.y, s4.y);
        m4.z = fmaxf(m4.z, s4.z); m4.w = fmaxf(m4.w, s4.w);
    }
#pragma unroll
    for (int o = 16; o; o >>= 1) {
        m4.x = fmaxf(m4.x, __shfl_xor_sync(0xffffffffu, m4.x, o));
        m4.y = fmaxf(m4.y, __shfl_xor_sync(0xffffffffu, m4.y, o));
        m4.z = fmaxf(m4.z, __shfl_xor_sync(0xffffffffu, m4.z, o));
        m4.w = fmaxf(m4.w, __shfl_xor_sync(0xffffffffu, m4.w, o));
    }
    if (lane == 0) red4[warp] = m4;
    __syncthreads();
    if (tid == 0) {
        float4 m = red4[0];
#pragma unroll
        for (int w = 1; w < 8; w++) {
            m.x = fmaxf(m.x, red4[w].x); m.y = fmaxf(m.y, red4[w].y);
            m.z = fmaxf(m.z, red4[w].z); m.w = fmaxf(m.w, red4[w].w);
        }
        s_mx4 = m;
    }
    __syncthreads();
    const float4 mx = s_mx4;

    // ---- softmax pass 2: exp + sum ----
    float4 sum4 = make_float4(0.f, 0.f, 0.f, 0.f);
    for (int ci = tid; ci < n; ci += 256) {
        float4 s4 = *(const float4*)&sc[ci][0];
        s4.x = __expf(s4.x - mx.x); s4.y = __expf(s4.y - mx.y);
        s4.z = __expf(s4.z - mx.z); s4.w = __expf(s4.w - mx.w);
        *(float4*)&sc[ci][0] = s4;
        sum4.x += s4.x; sum4.y += s4.y; sum4.z += s4.z; sum4.w += s4.w;
    }
#pragma unroll
    for (int o = 16; o; o >>= 1) {
        sum4.x += __shfl_xor_sync(0xffffffffu, sum4.x, o);
        sum4.y += __shfl_xor_sync(0xffffffffu, sum4.y, o);
        sum4.z += __shfl_xor_sync(0xffffffffu, sum4.z, o);
        sum4.w += __shfl_xor_sync(0xffffffffu, sum4.w, o);
    }
    if (lane == 0) red4[warp] = sum4;
    __syncthreads();
    if (tid == 0) {
        float4 s = red4[0];
#pragma unroll
        for (int w = 1; w < 8; w++) {
            s.x += red4[w].x; s.y += red4[w].y;
            s.z += red4[w].z; s.w += red4[w].w;
        }
        s_inv4 = make_float4(1.f/s.x, 1.f/s.y, 1.f/s.z, 1.f/s.w);
    }
    __syncthreads();

    // ---- V pass: 16 groups of 16 threads; one V load feeds 4 rows ----
    const int dg = tid & 15;
    const int gq = tid >> 4;
    float4 a0 = make_float4(0,0,0,0), a1 = a0, a2 = a0, a3 = a0;
    for (int ci = gq; ci < n; ci += 16) {
        float4 w4 = *(const float4*)&sc[ci][0];
        float4 v  = *(const float4*)&g_V[(bbase + cols[ci]) * H_SZ + dg * 4];
        a0.x += w4.x*v.x; a0.y += w4.x*v.y; a0.z += w4.x*v.z; a0.w += w4.x*v.w;
        a1.x += w4.y*v.x; a1.y += w4.y*v.y; a1.z += w4.y*v.z; a1.w += w4.y*v.w;
        a2.x += w4.z*v.x; a2.y += w4.z*v.y; a2.z += w4.z*v.z; a2.w += w4.z*v.w;
        a3.x += w4.w*v.x; a3.y += w4.w*v.y; a3.z += w4.w*v.z; a3.w += w4.w*v.w;
    }
    *(float4*)&outp[gq][0 * 64 + dg * 4] = a0;
    *(float4*)&outp[gq][1 * 64 + dg * 4] = a1;
    *(float4*)&outp[gq][2 * 64 + dg * 4] = a2;
    *(float4*)&outp[gq][3 * 64 + dg * 4] = a3;
    __syncthreads();

    // ---- final reduce + normalize ----
    {
        const int i = tid >> 6;
        const int d = tid & 63;
        float o = 0.f;
#pragma unroll
        for (int g2 = 0; g2 < 16; g2++) o += outp[g2][i * 64 + d];
        float inv = (i == 0) ? s_inv4.x : (i == 1) ? s_inv4.y
                  : (i == 2) ? s_inv4.z : s_inv4.w;
        out[((size_t)b * T_SZ + r0 + i) * H_SZ + d] = o * inv;
    }
}

// ---------------------------------------------------------------------------
// kernel_launch — inputs per metadata order: x, random_cols, Wk, Wq, Wv
// ---------------------------------------------------------------------------
extern "C" void kernel_launch(void* const* d_in, const int* in_sizes, int n_in,
                              void* d_out, int out_size)
{
    const float* x           = (const float*)d_in[0];
    const int*   random_cols = (const int*)  d_in[1];
    const float* Wk          = (const float*)d_in[2];
    const float* Wq          = (const float*)d_in[3];
    const float* Wv          = (const float*)d_in[4];
    float* out = (float*)d_out;

    proj_tc_kernel<<<BT / 64, 256>>>(x, Wq, Wk, Wv);

    attn4_kernel<<<BT / QR, 256>>>(random_cols, out);
}

// round 8
// speedup vs baseline: 2.1081x; 1.0441x over previous
#include <cuda_runtime.h>
#include <cuda_bf16.h>
#include <math.h>
#include <stdint.h>

// Problem constants
#define B_SZ 8
#define T_SZ 2048
#define C_SZ 1024
#define H_SZ 64
#define WIN 64
#define NGLOB 64
#define NRAND 64

#define BT (B_SZ * T_SZ)          // 16384 rows

// Scratch for projected q, k, v  (4 MB each) — device globals, no allocation.
__device__ float g_Q[BT * H_SZ];
__device__ float g_K[BT * H_SZ];
__device__ float g_V[BT * H_SZ];

__device__ __forceinline__ void mma_bf16(float* c, const uint32_t* a, const uint32_t* b) {
    asm volatile(
        "mma.sync.aligned.m16n8k16.row.col.f32.bf16.bf16.f32 "
        "{%0,%1,%2,%3}, {%4,%5,%6,%7}, {%8,%9}, {%0,%1,%2,%3};"
        : "+f"(c[0]), "+f"(c[1]), "+f"(c[2]), "+f"(c[3])
        : "r"(a[0]), "r"(a[1]), "r"(a[2]), "r"(a[3]),
          "r"(b[0]), "r"(b[1]));
}

// ---------------------------------------------------------------------------
// FUSED projection GEMM (Q,K,V) via 3x BF16-split mma.sync.m16n8k16,
// PING-PONG double-buffered smem: ONE barrier per K-chunk; the fill of
// chunk c+1 (LDG -> cvt -> STS) overlaps the MMA phase of chunk c.
//   iteration c:  sync                       (publishes buf[c&1]; frees buf[c&1^1])
//                 LDG chunk c+1              (scoreboard fills under MMA)
//                 MMA on buf[c&1]
//                 cvt+STS chunk c+1 -> buf[(c+1)&1]
// Layout per buffer identical to the verified round-7 kernel:
// word = bf16x2, 8 words/row pair-permuted [w0,w4,w1,w5,w2,w6,w3,w7]
// (fragment pair = one LDS.64), row stride 12 words, coalesced fill
// (thread i <-> row i>>3, word i&7), bank-conflict-free stores.
// ---------------------------------------------------------------------------
#define KC 16
#define PADK 12
#define NCHUNK (C_SZ / KC)        // 64

__global__ __launch_bounds__(256, 2) void proj_tc_kernel(
    const float* __restrict__ x,
    const float* __restrict__ Wq,
    const float* __restrict__ Wk,
    const float* __restrict__ Wv)
{
    __shared__ __align__(16) uint32_t sm_h[2][256][PADK];
    __shared__ __align__(16) uint32_t sm_l[2][256][PADK];

    const int m0   = blockIdx.x * 64;
    const int tid  = threadIdx.x;
    const int warp = tid >> 5;
    const int lane = tid & 31;
    const int grp  = lane >> 2;   // 0..7
    const int tig  = lane & 3;    // 0..3
    const int mh   = warp & 1;    // M half (32 rows)
    const int nq   = warp >> 1;   // N quarter (6 n-tiles)

    // ---- fill assignments: 8 float2 per thread ----
    const float* srcs[8];
    int rp[8];                    // word index within one buffer: row*PADK + p
#pragma unroll
    for (int it = 0; it < 8; it++) {
        const int i = it * 256 + tid;       // 0..2047
        int r, w;
        const float* base;
        if (it < 2) {                       // x: i in 0..511
            r = i >> 3; w = i & 7;
            base = &x[(size_t)(m0 + r) * C_SZ];
            rp[it] = r * PADK;
        } else {                            // W: j in 0..1535
            const int j = i - 512;
            r = j >> 3; w = j & 7;
            base = (r < 64)  ? &Wq[(size_t)r * C_SZ]
                 : (r < 128) ? &Wk[(size_t)(r - 64) * C_SZ]
                             : &Wv[(size_t)(r - 128) * C_SZ];
            rp[it] = (64 + r) * PADK;
        }
        srcs[it] = base + w * 2;
        rp[it] += 2 * (w & 3) + (w >> 2);   // pair-permute position
    }

    float acc[2][6][4];
#pragma unroll
    for (int mt = 0; mt < 2; mt++)
#pragma unroll
        for (int i = 0; i < 6; i++)
#pragma unroll
            for (int j = 0; j < 4; j++) acc[mt][i][j] = 0.f;

    // ---- prologue: load + store chunk 0 into buffer 0 ----
    float2 pf[8];
#pragma unroll
    for (int it = 0; it < 8; it++) pf[it] = *(const float2*)srcs[it];
#pragma unroll
    for (int it = 0; it < 8; it++) {
        const float a = pf[it].x, b = pf[it].y;
        __nv_bfloat162 h2 = __floats2bfloat162_rn(a, b);
        const uint32_t hu = *(const uint32_t*)&h2;
        const float ha = __uint_as_float(hu << 16);
        const float hb = __uint_as_float(hu & 0xFFFF0000u);
        __nv_bfloat162 l2 = __floats2bfloat162_rn(a - ha, b - hb);
        ((uint32_t*)sm_h[0])[rp[it]] = hu;
        ((uint32_t*)sm_l[0])[rp[it]] = *(const uint32_t*)&l2;
    }

    for (int c = 0; c < NCHUNK; c++) {
        __syncthreads();                    // buf[c&1] published; buf[c&1^1] free
        const int cur = c & 1;
        const bool more = (c + 1 < NCHUNK);

        // ---- issue next chunk's global loads ----
        if (more) {
            const int koff = (c + 1) * KC;
#pragma unroll
            for (int it = 0; it < 8; it++)
                pf[it] = *(const float2*)(srcs[it] + koff);
        }

        // ---- a-fragments from current buffer ----
        uint32_t ah[2][4], al[2][4];
#pragma unroll
        for (int mt = 0; mt < 2; mt++) {
            const int mrow = mh * 32 + mt * 16 + grp;
            uint2 q0 = *(const uint2*)&sm_h[cur][mrow][tig * 2];
            uint2 q1 = *(const uint2*)&sm_h[cur][mrow + 8][tig * 2];
            ah[mt][0] = q0.x; ah[mt][2] = q0.y;
            ah[mt][1] = q1.x; ah[mt][3] = q1.y;
            uint2 s0 = *(const uint2*)&sm_l[cur][mrow][tig * 2];
            uint2 s1 = *(const uint2*)&sm_l[cur][mrow + 8][tig * 2];
            al[mt][0] = s0.x; al[mt][2] = s0.y;
            al[mt][1] = s1.x; al[mt][3] = s1.y;
        }

        // ---- b-fragments + MMAs ----
#pragma unroll
        for (int i = 0; i < 6; i++) {
            const int wrow = 64 + (nq * 6 + i) * 8 + grp;
            uint2 bh2 = *(const uint2*)&sm_h[cur][wrow][tig * 2];
            uint2 bl2 = *(const uint2*)&sm_l[cur][wrow][tig * 2];
            uint32_t bh[2] = {bh2.x, bh2.y};
            uint32_t bl[2] = {bl2.x, bl2.y};
#pragma unroll
            for (int mt = 0; mt < 2; mt++) {
                mma_bf16(acc[mt][i], al[mt], bh);   // lo*hi
                mma_bf16(acc[mt][i], ah[mt], bl);   // hi*lo
                mma_bf16(acc[mt][i], ah[mt], bh);   // hi*hi
            }
        }

        // ---- convert + store next chunk into the other buffer ----
        if (more) {
            const int nxt = cur ^ 1;
#pragma unroll
            for (int it = 0; it < 8; it++) {
                const float a = pf[it].x, b = pf[it].y;
                __nv_bfloat162 h2 = __floats2bfloat162_rn(a, b);
                const uint32_t hu = *(const uint32_t*)&h2;
                const float ha = __uint_as_float(hu << 16);
                const float hb = __uint_as_float(hu & 0xFFFF0000u);
                __nv_bfloat162 l2 = __floats2bfloat162_rn(a - ha, b - hb);
                ((uint32_t*)sm_h[nxt])[rp[it]] = hu;
                ((uint32_t*)sm_l[nxt])[rp[it]] = *(const uint32_t*)&l2;
            }
        }
    }

    // ---- epilogue: c0=(grp,2tig), c1=+1, c2=(grp+8,2tig), c3=+1 ----
#pragma unroll
    for (int mt = 0; mt < 2; mt++) {
        const int mwr = m0 + mh * 32 + mt * 16 + grp;
#pragma unroll
        for (int i = 0; i < 6; i++) {
            const int ntg = nq * 6 + i;
            float* out = (ntg < 8) ? g_Q : (ntg < 16) ? g_K : g_V;
            const int col = (ntg & 7) * 8 + tig * 2;
            *(float2*)&out[(size_t)mwr * H_SZ + col] =
                make_float2(acc[mt][i][0], acc[mt][i][1]);
            *(float2*)&out[(size_t)(mwr + 8) * H_SZ + col] =
                make_float2(acc[mt][i][2], acc[mt][i][3]);
        }
    }
}

// ---------------------------------------------------------------------------
// Sparse BigBird attention, 4 query rows per block (UNCHANGED, passing).
// ---------------------------------------------------------------------------
#define QR 4
#define MAXC 392

__global__ __launch_bounds__(256) void attn4_kernel(
    const int* __restrict__ random_cols,
    float* __restrict__ out)
{
    const int blk = blockIdx.x;            // 0 .. 4095
    const int b   = blk >> 9;              // 512 blocks per batch
    const int r0  = (blk & 511) * QR;
    const int r3  = r0 + 3;

    __shared__ int   cols[MAXC];
    __shared__ __align__(16) float sc[MAXC][4];
    __shared__ __align__(16) float qs[QR][H_SZ];
    __shared__ uint32_t rbit[QR][64];
    __shared__ uint32_t ubit[64];
    __shared__ int   s_n;
    __shared__ __align__(16) float4 red4[8];
    __shared__ float4 s_mx4, s_inv4;
    __shared__ __align__(16) float outp[16][256];   // [group][row*64+dim]

    const int tid  = threadIdx.x;
    const int lane = tid & 31;
    const int warp = tid >> 5;
    const int i4   = tid >> 6;    // 0..3  (row for setup)
    const int j4   = tid & 63;    // 0..63

    // ---- phase 0: init + loads ----
    rbit[i4][j4] = 0;                          // 256 words exactly
    if (tid < 64) ubit[tid] = 0;
    if (tid == 0) s_n = 0;
    const int myrnd = random_cols[(r0 + i4) * NRAND + j4];
    qs[i4][j4] = g_Q[((size_t)b * T_SZ + r0 + i4) * H_SZ + j4];

    const int lo0 = max(0, r0 - (WIN - 1));
    const int gn  = min(NGLOB, r3 + 1);
    const int l0u = max(64, lo0);
    const int ln  = max(0, r3 - l0u + 1);
    __syncthreads();

    // ---- phase 1: bitmaps + union list ----
    atomicOr(&rbit[i4][myrnd >> 5], 1u << (myrnd & 31));
    if (tid < gn) cols[tid] = tid;
    if (tid >= 64 && tid < 64 + ln) cols[gn + tid - 64] = l0u + (tid - 64);
    if (myrnd >= 64 && myrnd < lo0) {          // only range not covered above
        uint32_t bit = 1u << (myrnd & 31);
        uint32_t old = atomicOr(&ubit[myrnd >> 5], bit);
        if (!(old & bit)) {
            int p = atomicAdd(&s_n, 1);
            cols[gn + ln + p] = myrnd;
        }
    }
    __syncthreads();
    const int n = gn + ln + s_n;

    // ---- score pass: 8-lane groups, 4 dots per K load ----
    const int l8 = lane & 7;
    const int g8 = lane >> 3;
    float4 qA[QR], qB[QR];
#pragma unroll
    for (int i = 0; i < QR; i++) {
        qA[i] = *(const float4*)&qs[i][l8 * 8];
        qB[i] = *(const float4*)&qs[i][l8 * 8 + 4];
    }
    const size_t bbase = (size_t)b * T_SZ;

    for (int ci0 = warp * 4; ci0 < n; ci0 += 32) {     // warp-uniform bound
        const int  ci  = ci0 + g8;
        const bool act = (ci < n);
        const int  c   = cols[act ? ci : 0];
        const float* kp = &g_K[(bbase + c) * H_SZ + l8 * 8];
        float4 ka = *(const float4*)kp;
        float4 kb = *(const float4*)(kp + 4);
        float p0 = qA[0].x*ka.x + qA[0].y*ka.y + qA[0].z*ka.z + qA[0].w*ka.w
                 + qB[0].x*kb.x + qB[0].y*kb.y + qB[0].z*kb.z + qB[0].w*kb.w;
        float p1 = qA[1].x*ka.x + qA[1].y*ka.y + qA[1].z*ka.z + qA[1].w*ka.w
                 + qB[1].x*kb.x + qB[1].y*kb.y + qB[1].z*kb.z + qB[1].w*kb.w;
        float p2 = qA[2].x*ka.x + qA[2].y*ka.y + qA[2].z*ka.z + qA[2].w*ka.w
                 + qB[2].x*kb.x + qB[2].y*kb.y + qB[2].z*kb.z + qB[2].w*kb.w;
        float p3 = qA[3].x*ka.x + qA[3].y*ka.y + qA[3].z*ka.z + qA[3].w*ka.w
                 + qB[3].x*kb.x + qB[3].y*kb.y + qB[3].z*kb.z + qB[3].w*kb.w;
#pragma unroll
        for (int o = 4; o; o >>= 1) {
            p0 += __shfl_xor_sync(0xffffffffu, p0, o);
            p1 += __shfl_xor_sync(0xffffffffu, p1, o);
            p2 += __shfl_xor_sync(0xffffffffu, p2, o);
            p3 += __shfl_xor_sync(0xffffffffu, p3, o);
        }
        if (act && l8 < QR) {
            const int ri = r0 + l8;
            float pv = (l8 == 0) ? p0 : (l8 == 1) ? p1 : (l8 == 2) ? p2 : p3;
            bool allowed = (c <= ri) &&
                           ((c > ri - WIN) || (c < NGLOB) ||
                            ((rbit[l8][c >> 5] >> (c & 31)) & 1u));
            sc[ci][l8] = allowed ? pv * 0.125f : -INFINITY;
        }
    }
    __syncthreads();

    // ---- softmax pass 1: componentwise max over 4 rows ----
    float4 m4 = make_float4(-1e30f, -1e30f, -1e30f, -1e30f);
    for (int ci = tid; ci < n; ci += 256) {
        float4 s4 = *(const float4*)&sc[ci][0];
        m4.x = fmaxf(m4.x, s4.x); m4.y = fmaxf(m4.y, s4.y);
        m4.z = fmaxf(m4.z, s4.z); m4.w = fmaxf(m4.w, s4.w);
    }
#pragma unroll
    for (int o = 16; o; o >>= 1) {
        m4.x = fmaxf(m4.x, __shfl_xor_sync(0xffffffffu, m4.x, o));
        m4.y = fmaxf(m4.y, __shfl_xor_sync(0xffffffffu, m4.y, o));
        m4.z = fmaxf(m4.z, __shfl_xor_sync(0xffffffffu, m4.z, o));
        m4.w = fmaxf(m4.w, __shfl_xor_sync(0xffffffffu, m4.w, o));
    }
    if (lane == 0) red4[warp] = m4;
    __syncthreads();
    if (tid == 0) {
        float4 m = red4[0];
#pragma unroll
        for (int w = 1; w < 8; w++) {
            m.x = fmaxf(m.x, red4[w].x); m.y = fmaxf(m.y, red4[w].y);
            m.z = fmaxf(m.z, red4[w].z); m.w = fmaxf(m.w, red4[w].w);
        }
        s_mx4 = m;
    }
    __syncthreads();
    const float4 mx = s_mx4;

    // ---- softmax pass 2: exp + sum ----
    float4 sum4 = make_float4(0.f, 0.f, 0.f, 0.f);
    for (int ci = tid; ci < n; ci += 256) {
        float4 s4 = *(const float4*)&sc[ci][0];
        s4.x = __expf(s4.x - mx.x); s4.y = __expf(s4.y - mx.y);
        s4.z = __expf(s4.z - mx.z); s4.w = __expf(s4.w - mx.w);
        *(float4*)&sc[ci][0] = s4;
        sum4.x += s4.x; sum4.y += s4.y; sum4.z += s4.z; sum4.w += s4.w;
    }
#pragma unroll
    for (int o = 16; o; o >>= 1) {
        sum4.x += __shfl_xor_sync(0xffffffffu, sum4.x, o);
        sum4.y += __shfl_xor_sync(0xffffffffu, sum4.y, o);
        sum4.z += __shfl_xor_sync(0xffffffffu, sum4.z, o);
        sum4.w += __shfl_xor_sync(0xffffffffu, sum4.w, o);
    }
    if (lane == 0) red4[warp] = sum4;
    __syncthreads();
    if (tid == 0) {
        float4 s = red4[0];
#pragma unroll
        for (int w = 1; w < 8; w++) {
            s.x += red4[w].x; s.y += red4[w].y;
            s.z += red4[w].z; s.w += red4[w].w;
        }
        s_inv4 = make_float4(1.f/s.x, 1.f/s.y, 1.f/s.z, 1.f/s.w);
    }
    __syncthreads();

    // ---- V pass: 16 groups of 16 threads; one V load feeds 4 rows ----
    const int dg = tid & 15;
    const int gq = tid >> 4;
    float4 a0 = make_float4(0,0,0,0), a1 = a0, a2 = a0, a3 = a0;
    for (int ci = gq; ci < n; ci += 16) {
        float4 w4 = *(const float4*)&sc[ci][0];
        float4 v  = *(const float4*)&g_V[(bbase + cols[ci]) * H_SZ + dg * 4];
        a0.x += w4.x*v.x; a0.y += w4.x*v.y; a0.z += w4.x*v.z; a0.w += w4.x*v.w;
        a1.x += w4.y*v.x; a1.y += w4.y*v.y; a1.z += w4.y*v.z; a1.w += w4.y*v.w;
        a2.x += w4.z*v.x; a2.y += w4.z*v.y; a2.z += w4.z*v.z; a2.w += w4.z*v.w;
        a3.x += w4.w*v.x; a3.y += w4.w*v.y; a3.z += w4.w*v.z; a3.w += w4.w*v.w;
    }
    *(float4*)&outp[gq][0 * 64 + dg * 4] = a0;
    *(float4*)&outp[gq][1 * 64 + dg * 4] = a1;
    *(float4*)&outp[gq][2 * 64 + dg * 4] = a2;
    *(float4*)&outp[gq][3 * 64 + dg * 4] = a3;
    __syncthreads();

    // ---- final reduce + normalize ----
    {
        const int i = tid >> 6;
        const int d = tid & 63;
        float o = 0.f;
#pragma unroll
        for (int g2 = 0; g2 < 16; g2++) o += outp[g2][i * 64 + d];
        float inv = (i == 0) ? s_inv4.x : (i == 1) ? s_inv4.y
                  : (i == 2) ? s_inv4.z : s_inv4.w;
        out[((size_t)b * T_SZ + r0 + i) * H_SZ + d] = o * inv;
    }
}

// ---------------------------------------------------------------------------
// kernel_launch — inputs per metadata order: x, random_cols, Wk, Wq, Wv
// ---------------------------------------------------------------------------
extern "C" void kernel_launch(void* const* d_in, const int* in_sizes, int n_in,
                              void* d_out, int out_size)
{
    const float* x           = (const float*)d_in[0];
    const int*   random_cols = (const int*)  d_in[1];
    const float* Wk          = (const float*)d_in[2];
    const float* Wq          = (const float*)d_in[3];
    const float* Wv          = (const float*)d_in[4];
    float* out = (float*)d_out;

    proj_tc_kernel<<<BT / 64, 256>>>(x, Wq, Wk, Wv);

    attn4_kernel<<<BT / QR, 256>>>(random_cols, out);
}